// round 8
// baseline (speedup 1.0000x reference)
#include <cuda_runtime.h>

// Problem constants
#define BB   4      // batch
#define CIN  3
#define C1   32     // conv1 out channels (16x16 spatial)
#define C2   64     // conv2 out channels (8x8 spatial)
#define MM   512    // hopfield memory slots
#define DD   64     // token dim (== C2)
#define NTOK 2      // tokens per hopfield block
#define THR  1024   // threads per block (32 warps -> 8 per SMSP)
#define NBLK 128    // blocks (1 per SM, <= 148 -> all co-resident)
#define LSTR 68     // Lsm row stride (floats): 16B-aligned, conflict-free

// Padded conv1-output layout: [b][ic][18][18] float2 {a1, v1}.
// Halo never written -> stays zero from static init (deterministic).
#define AVROW 18
#define AVPL  (AVROW*AVROW)

// Scratch (allocation-free rule: __device__ globals; zero-initialized)
__device__ float2 g_av[BB*C1*AVPL];   // padded {a1, v1}
__device__ float  g_zq[BB*C2*64];     // masked JVP output (B, C2, 64 spatial)
__device__ float  g_Wc[DD*DD];        // Wv @ Wo (folded projection)
__device__ unsigned g_bar;            // cumulative grid-barrier ticket counter

// Software grid barrier: all NBLK blocks co-resident (1 block/SM). 2 barriers
// * 128 arrivals per launch = 256; 2^32 % 256 == 0 so wrap is safe.
__device__ __forceinline__ void grid_barrier() {
    __syncthreads();
    if (threadIdx.x == 0) {
        __threadfence();
        unsigned ticket = atomicAdd(&g_bar, 1u);
        unsigned target = (ticket & ~(unsigned)(NBLK - 1)) + NBLK;
        while ((int)(*(volatile unsigned*)&g_bar - target) < 0) { }
        __threadfence();
    }
    __syncthreads();
}

// Shared memory layout (float offsets)
#define LSM_OFF   0                       // 512*68 = 34816
#define WCS_OFF   34816                   // 64*64  = 4096
#define PS_OFF    38912                   // 1024 f: probs [j][512]
#define PART_OFF  39936                   // 1024 f: partials [j][8][64]
#define TS_OFF    40960                   // 128 f: tokens [j][64]
#define OS2_OFF   41088                   // 64 float2 = 128 f
#define RED_OFF   41216                   // 40 f: warp-reduce scratch
#define XPAD_OFF  41256                   // 3*34*34 = 3468 f
#define SMEM_FLOATS (XPAD_OFF + 3*34*34)  // 44724 floats = 178896 B

__global__ __launch_bounds__(THR, 1)
void fused_kernel(const float* __restrict__ x,
                  const float* __restrict__ w1,
                  const float* __restrict__ b1,
                  const float* __restrict__ w2,
                  const float* __restrict__ b2,
                  const float* __restrict__ lookup,
                  const float* __restrict__ Wv,
                  const float* __restrict__ Wo,
                  float* __restrict__ out) {
    extern __shared__ float smem[];
    float*  Lsm   = smem + LSM_OFF;
    float*  WcS   = smem + WCS_OFF;
    float*  pS    = smem + PS_OFF;        // [j][512]
    float*  part  = smem + PART_OFF;      // [j][8][64]
    float*  tS    = smem + TS_OFF;        // [j][64]
    float2* oS2   = (float2*)(smem + OS2_OFF);
    float*  red   = smem + RED_OFF;       // 32 warp results + 2 MX + 2 SUM
    float*  xpad  = smem + XPAD_OFF;      // [3][34][34] zero-padded

    int tid  = threadIdx.x;
    int lane = tid & 31;
    int wid  = tid >> 5;
    int blk  = blockIdx.x;
    int gtid = blk * THR + tid;           // 0..131071

    // ===== Phase 0a: zero the padded x tile ================================
    #pragma unroll
    for (int it = 0; it < 4; it++) {
        int i = it*THR + tid;
        if (i < 3*34*34) xpad[i] = 0.f;
    }
    __syncthreads();

    // ===== Phase 0b: stage lookup -> Lsm (MLP=8), x[b] -> xpad interior ====
    {
        const float4* L4   = (const float4*)lookup;
        float4*       Lsm4 = (float4*)Lsm;         // row stride 17 float4
        float4 v[8];
        #pragma unroll
        for (int u = 0; u < 8; u++)
            v[u] = __ldg(&L4[u*THR + tid]);
        #pragma unroll
        for (int u = 0; u < 8; u++) {
            int f = u*THR + tid;                   // float4 index
            Lsm4[(f >> 4)*17 + (f & 15)] = v[u];
        }
    }
    {
        int cb = blk >> 5;                         // this block's batch sample
        const float* xb = x + cb * CIN * 1024;
        #pragma unroll
        for (int it = 0; it < 3; it++) {
            int i = it*THR + tid;                  // < 3072
            int ic = i >> 10, r = (i >> 5) & 31, c = i & 31;
            xpad[(ic*34 + r + 1)*34 + c + 1] = __ldg(&xb[i]);
        }
    }
    __syncthreads();

    // ===== Phase 1: conv1 (4 thr/output, ky split) + Wc ====================
    {
        int cb  = blk >> 5;         // batch
        int oc  = blk & 31;         // conv1 out channel (one per block)
        int o   = tid >> 2;         // output 0..255
        int ky  = tid & 3;          // ky split across 4 lanes
        int oy = o >> 4, ox = o & 15;

        float s = 0.f;
        #pragma unroll
        for (int ic = 0; ic < CIN; ic++) {
            const float* row = &xpad[(ic*34 + oy*2 + ky)*34 + ox*2];
            float4 w4 = __ldg((const float4*)&w1[(oc*CIN + ic)*16 + ky*4]);
            s += row[0]*w4.x + row[1]*w4.y + row[2]*w4.z + row[3]*w4.w;
        }
        s += __shfl_xor_sync(0xFFFFFFFFu, s, 1);
        s += __shfl_xor_sync(0xFFFFFFFFu, s, 2);
        if (ky == 0) {
            float pre = s + b1[oc];
            bool on = pre > 0.f;
            g_av[(cb*C1 + oc)*AVPL + (oy + 1)*AVROW + (ox + 1)] =
                make_float2(on ? pre : 0.f, on ? s : 0.f);
        }
        // Wc = Wv @ Wo: 32 elems per block on threads 0..31
        if (tid < 32) {
            int i = blk*32 + tid;
            int d = i >> 6, e = i & 63;
            float ws = 0.f;
            #pragma unroll 16
            for (int k = 0; k < DD; k++)
                ws += __ldg(&Wv[d*DD + k]) * __ldg(&Wo[k*DD + e]);
            g_Wc[i] = ws;
        }
    }
    grid_barrier();

    // ===== Phase 2: conv2 (8 thr/output, ic split 8-way, branch-free) ======
    {
        int h  = gtid & 7;           // ic eighth
        int p  = gtid >> 3;          // output index, < 16384
        int ox = p & 7;
        int oy = (p >> 3) & 7;
        int oc = (p >> 6) & 63;
        int cb = p >> 12;

        float sA = 0.f, sV = 0.f;
        int ic0 = h * 4;
        #pragma unroll
        for (int ic = ic0; ic < ic0 + 4; ic++) {
            const float2* avp = &g_av[(cb*C1 + ic)*AVPL];
            const float4* wp4 = (const float4*)&w2[(oc*C1 + ic)*16];
            #pragma unroll
            for (int ky = 0; ky < 4; ky++) {
                float4 w4 = __ldg(&wp4[ky]);
                const float2* row = &avp[(oy*2 + ky)*AVROW + ox*2];
                float2 a0 = __ldg(&row[0]);
                float2 a1 = __ldg(&row[1]);
                float2 a2 = __ldg(&row[2]);
                float2 a3 = __ldg(&row[3]);
                sA += a0.x*w4.x + a1.x*w4.y + a2.x*w4.z + a3.x*w4.w;
                sV += a0.y*w4.x + a1.y*w4.y + a2.y*w4.z + a3.y*w4.w;
            }
        }
        sA += __shfl_xor_sync(0xFFFFFFFFu, sA, 1);
        sV += __shfl_xor_sync(0xFFFFFFFFu, sV, 1);
        sA += __shfl_xor_sync(0xFFFFFFFFu, sA, 2);
        sV += __shfl_xor_sync(0xFFFFFFFFu, sV, 2);
        sA += __shfl_xor_sync(0xFFFFFFFFu, sA, 4);
        sV += __shfl_xor_sync(0xFFFFFFFFu, sV, 4);
        if (h == 0) {
            float pre = sA + b2[oc];
            g_zq[(cb*C2 + oc)*64 + (oy*8 + ox)] = (pre > 0.f) ? sV : 0.f;
        }
    }
    grid_barrier();

    // ===== Phase 3: hopfield (2 tokens/block) ==============================
    int n0 = (blk & 31) * NTOK;
    int b  = blk >> 5;
    int m  = tid & 511;               // memory slot
    int j  = tid >> 9;                // token (0/1); warps 0-15 j=0, 16-31 j=1

    {   // stage Wc: 1 float4 each
        ((float4*)WcS)[tid] = __ldg(&((const float4*)g_Wc)[tid]);
    }
    if (tid < DD*NTOK) {              // tokens [j][d]
        int jj = tid >> 6, d = tid & 63;
        tS[jj*DD + d] = g_zq[(b*C2 + d)*64 + n0 + jj];
    }
    __syncthreads();

    // --- scores: thread owns (m, j) ---
    float a = 0.f;
    {
        const float4* lrow = (const float4*)&Lsm[m*LSTR];
        const float4* trow = (const float4*)&tS[j*DD];
        #pragma unroll
        for (int q = 0; q < 16; q++) {
            float4 l = lrow[q];
            float4 t = trow[q];
            a += l.x*t.x + l.y*t.y + l.z*t.z + l.w*t.w;
        }
    }
    a *= 0.125f;   // 1/sqrt(64)

    // --- per-j max over 512 threads (16 warps each) ---
    {
        float mx = a;
        #pragma unroll
        for (int o = 16; o > 0; o >>= 1)
            mx = fmaxf(mx, __shfl_xor_sync(0xFFFFFFFFu, mx, o));
        if (lane == 0) red[wid] = mx;
    }
    __syncthreads();
    if (tid < 32) {   // lanes 0-15 reduce j0 warps, 16-31 reduce j1 warps
        float v = red[lane];
        #pragma unroll
        for (int o = 8; o > 0; o >>= 1)
            v = fmaxf(v, __shfl_xor_sync(0xFFFFFFFFu, v, o));
        if ((lane & 15) == 0) red[32 + (lane >> 4)] = v;
    }
    __syncthreads();
    float MX = red[32 + j];

    // --- exp + per-j sum ---
    float e = __expf(a - MX);
    pS[j*512 + m] = e;
    {
        float s = e;
        #pragma unroll
        for (int o = 16; o > 0; o >>= 1)
            s += __shfl_xor_sync(0xFFFFFFFFu, s, o);
        if (lane == 0) red[wid] = s;
    }
    __syncthreads();
    if (tid < 32) {
        float v = red[lane];
        #pragma unroll
        for (int o = 8; o > 0; o >>= 1)
            v += __shfl_xor_sync(0xFFFFFFFFu, v, o);
        if ((lane & 15) == 0) red[34 + (lane >> 4)] = v;
    }
    __syncthreads();

    // --- retrieval: part[j][c][d] = sum over 64 m of p[j][m]*L[m][d] ---
    {
        int d = tid & 63, c = (tid >> 6) & 7;   // j = tid>>9
        float r = 0.f;
        int m0 = c * 64;
        const float* pj = &pS[j*512];
        #pragma unroll 8
        for (int mm = 0; mm < 64; mm++) {
            float p = pj[m0 + mm];                // broadcast
            float l = Lsm[(m0 + mm)*LSTR + d];    // conflict-free
            r += p*l;
        }
        part[(j*8 + c)*64 + d] = r;
    }
    __syncthreads();
    if (tid < NTOK*DD) {
        int jj = tid >> 6, d = tid & 63;
        float s = 0.f;
        #pragma unroll
        for (int c = 0; c < 8; c++)
            s += part[(jj*8 + c)*64 + d];
        tS[jj*DD + d] = s / red[34 + jj];         // tmp[j][d] (tS reused)
    }
    __syncthreads();

    // --- projection: out[j][e] = sum_d tmp[j][d] * Wc[d][e] ---
    if (tid < NTOK*DD) {
        int jj = tid >> 6, ee = tid & 63;
        float o = 0.f;
        const float* tp = &tS[jj*DD];
        #pragma unroll 16
        for (int d = 0; d < DD; d++)
            o += tp[d] * WcS[d*DD + ee];          // bcast + conflict-free
        ((float*)&oS2[ee])[jj] = o;
    }
    __syncthreads();
    if (tid < DD) {
        float2 ov = oS2[tid];
        *(float2*)&out[(b*C2 + tid)*64 + n0] = ov;
    }
}

// ---------------------------------------------------------------------------
extern "C" void kernel_launch(void* const* d_in, const int* in_sizes, int n_in,
                              void* d_out, int out_size) {
    const float* x       = (const float*)d_in[0];
    const float* conv1_w = (const float*)d_in[1];
    const float* conv1_b = (const float*)d_in[2];
    const float* conv2_w = (const float*)d_in[3];
    const float* conv2_b = (const float*)d_in[4];
    const float* lookup  = (const float*)d_in[5];
    const float* Wv      = (const float*)d_in[6];
    const float* Wo      = (const float*)d_in[7];
    float* out = (float*)d_out;

    const size_t smem_bytes = SMEM_FLOATS * sizeof(float);

    cudaFuncSetAttribute(fused_kernel,
                         cudaFuncAttributeMaxDynamicSharedMemorySize,
                         (int)smem_bytes);
    cudaFuncSetAttribute(fused_kernel,
                         cudaFuncAttributePreferredSharedMemoryCarveout, 100);

    fused_kernel<<<NBLK, THR, smem_bytes>>>(
        x, conv1_w, conv1_b, conv2_w, conv2_b, lookup, Wv, Wo, out);
}

// round 9
// speedup vs baseline: 2.3473x; 2.3473x over previous
#include <cuda_runtime.h>

// Problem constants
#define BB   4      // batch
#define CIN  3
#define C1   32     // conv1 out channels (16x16 spatial)
#define C2   64     // conv2 out channels (8x8 spatial)
#define MM   512    // hopfield memory slots
#define DD   64     // token dim (== C2)
#define NTOK 2      // tokens per block
#define THR  512    // threads per block
#define NBLK 128    // 4 samples x 32 token-pairs; fully independent blocks
#define LSTR 68     // Lsm row stride (floats): 16B-aligned, conflict-free

// Shared memory layout (float offsets). Everything lives in smem; the only
// gmem traffic is input staging + the final output store. No barriers, no
// device-global scratch.
#define LSM_OFF   0                        // 512*68 = 34816
#define WVS_OFF   34816                    // 64*64  = 4096
#define WOS_OFF   38912                    // 64*64  = 4096
#define PS2_OFF   43008                    // 512 float2 = 1024 f
#define PART2_OFF 44032                    // 512 float2 = 1024 f
#define ZQ_OFF    45056                    // [2][64] tokens / tmp = 128 f
#define S1_OFF    45184                    // [2][64] = 128 f
#define OS2_OFF   45312                    // 64 float2 = 128 f
#define RED_OFF   45440                    // 40 f reduce scratch
#define XPAD_OFF  45480                    // 3*34*34 = 3468 f
#define AW_OFF    48948                    // 32*25 = 800 f (stride-25: conflict-free)
#define VW_OFF    49748                    // 32*25 = 800 f
#define SMEM_FLOATS 50548                  // 202192 bytes

__global__ __launch_bounds__(THR, 1)
void fused_kernel(const float* __restrict__ x,
                  const float* __restrict__ w1,
                  const float* __restrict__ b1,
                  const float* __restrict__ w2,
                  const float* __restrict__ b2,
                  const float* __restrict__ lookup,
                  const float* __restrict__ Wv,
                  const float* __restrict__ Wo,
                  float* __restrict__ out) {
    extern __shared__ float smem[];
    float*  Lsm   = smem + LSM_OFF;
    float*  WvS   = smem + WVS_OFF;
    float*  WoS   = smem + WOS_OFF;
    float2* pS2   = (float2*)(smem + PS2_OFF);
    float2* part2 = (float2*)(smem + PART2_OFF);
    float*  zqS   = smem + ZQ_OFF;        // [j][64]: tokens, later tmp
    float*  s1S   = smem + S1_OFF;        // [j][64]: first projection
    float2* oS2   = (float2*)(smem + OS2_OFF);
    float2* red2  = (float2*)(smem + RED_OFF);
    float*  xpad  = smem + XPAD_OFF;      // [3][34][34] zero-padded input
    float*  aW    = smem + AW_OFF;        // conv1 window, relu(pre)
    float*  vW    = smem + VW_OFF;        // conv1 window, masked JVP

    int tid  = threadIdx.x;
    int lane = tid & 31;
    int wid  = tid >> 5;
    int blk  = blockIdx.x;
    int b    = blk >> 5;                  // sample
    int tg   = blk & 31;                  // token group
    int n0   = tg * NTOK;
    int oy   = n0 >> 3;                   // both tokens share oy (n0 even)
    int ox0  = n0 & 7;

    // ===== Stage 0a: zero the padded x tile ================================
    #pragma unroll
    for (int it = 0; it < 7; it++) {
        int i = it*THR + tid;
        if (i < 3*34*34) xpad[i] = 0.f;
    }
    __syncthreads();

    // ===== Stage 0b: lookup -> Lsm (MLP=8), Wv/Wo -> smem, x[b] interior ===
    {
        const float4* L4   = (const float4*)lookup;
        float4*       Lsm4 = (float4*)Lsm;         // row stride 17 float4
        #pragma unroll
        for (int batch = 0; batch < 2; batch++) {
            float4 v[8];
            #pragma unroll
            for (int u = 0; u < 8; u++)
                v[u] = __ldg(&L4[(batch*8 + u)*THR + tid]);
            #pragma unroll
            for (int u = 0; u < 8; u++) {
                int f = (batch*8 + u)*THR + tid;   // float4 index
                Lsm4[(f >> 4)*17 + (f & 15)] = v[u];
            }
        }
    }
    {
        const float4* Wv4 = (const float4*)Wv;
        const float4* Wo4 = (const float4*)Wo;
        ((float4*)WvS)[tid]       = __ldg(&Wv4[tid]);
        ((float4*)WvS)[tid + THR] = __ldg(&Wv4[tid + THR]);
        ((float4*)WoS)[tid]       = __ldg(&Wo4[tid]);
        ((float4*)WoS)[tid + THR] = __ldg(&Wo4[tid + THR]);
    }
    {
        const float* xb = x + b * CIN * 1024;
        #pragma unroll
        for (int it = 0; it < 6; it++) {
            int i = it*THR + tid;                  // < 3072
            int ic = i >> 10, r = (i >> 5) & 31, c = i & 31;
            xpad[(ic*34 + r + 1)*34 + c + 1] = __ldg(&xb[i]);
        }
    }
    __syncthreads();

    // ===== Phase 1: conv1 for just the 4x6 window this block needs =========
    // window entry (ic, ri, ci) -> conv1 output at (r = 2oy-1+ri, c = 2ox0-1+ci)
    for (int e = tid; e < 32*24; e += THR) {
        int ic  = e / 24;
        int pos = e - ic*24;
        int ri  = pos / 6;
        int ci  = pos - ri*6;
        int r = 2*oy - 1 + ri;
        int c = 2*ox0 - 1 + ci;
        float aVal = 0.f, vVal = 0.f;
        if ((unsigned)r < 16u && (unsigned)c < 16u) {
            float s = 0.f;
            #pragma unroll
            for (int cin = 0; cin < CIN; cin++) {
                // input tap (2r-1+ky, 2c-1+kx) + pad(1) => xpad[2r+ky][2c+kx]
                const float* base = &xpad[(cin*34 + 2*r)*34 + 2*c];
                const float4* wp4 = (const float4*)&w1[(ic*CIN + cin)*16];
                #pragma unroll
                for (int ky = 0; ky < 4; ky++) {
                    float4 w4 = __ldg(&wp4[ky]);
                    const float* row = base + ky*34;
                    s += row[0]*w4.x + row[1]*w4.y + row[2]*w4.z + row[3]*w4.w;
                }
            }
            float pre = s + __ldg(&b1[ic]);
            if (pre > 0.f) { aVal = pre; vVal = s; }
        }
        aW[ic*25 + pos] = aVal;
        vW[ic*25 + pos] = vVal;
    }
    __syncthreads();

    // ===== Phase 2: conv2 from smem window ================================
    // warp wid -> oc group {4*wid .. 4*wid+3}; lane -> ic. Shuffle-reduce ic.
    {
        int ic = lane;
        float sA[4][2] = {}, sV[4][2] = {};
        const float4* w24 = (const float4*)w2;
        #pragma unroll
        for (int ky = 0; ky < 4; ky++) {
            const float* ar = &aW[ic*25 + ky*6];
            const float* vr = &vW[ic*25 + ky*6];
            float a0=ar[0], a1=ar[1], a2=ar[2], a3=ar[3], a4=ar[4], a5=ar[5];
            float v0=vr[0], v1=vr[1], v2=vr[2], v3=vr[3], v4=vr[4], v5=vr[5];
            #pragma unroll
            for (int o4 = 0; o4 < 4; o4++) {
                float4 w4 = __ldg(&w24[((wid*4 + o4)*C1 + ic)*4 + ky]);
                sA[o4][0] += a0*w4.x + a1*w4.y + a2*w4.z + a3*w4.w;
                sV[o4][0] += v0*w4.x + v1*w4.y + v2*w4.z + v3*w4.w;
                sA[o4][1] += a2*w4.x + a3*w4.y + a4*w4.z + a5*w4.w;
                sV[o4][1] += v2*w4.x + v3*w4.y + v4*w4.z + v5*w4.w;
            }
        }
        #pragma unroll
        for (int o4 = 0; o4 < 4; o4++)
            #pragma unroll
            for (int jj = 0; jj < 2; jj++)
                #pragma unroll
                for (int off = 16; off > 0; off >>= 1) {
                    sA[o4][jj] += __shfl_xor_sync(0xFFFFFFFFu, sA[o4][jj], off);
                    sV[o4][jj] += __shfl_xor_sync(0xFFFFFFFFu, sV[o4][jj], off);
                }
        if (lane == 0) {
            #pragma unroll
            for (int o4 = 0; o4 < 4; o4++) {
                int oc = wid*4 + o4;
                float bb = __ldg(&b2[oc]);
                #pragma unroll
                for (int jj = 0; jj < 2; jj++) {
                    float pre = sA[o4][jj] + bb;
                    zqS[jj*DD + oc] = (pre > 0.f) ? sV[o4][jj] : 0.f;
                }
            }
        }
    }
    __syncthreads();

    // ===== Phase 3: hopfield ==============================================
    // scores: thread owns row m = tid, both tokens
    float a0 = 0.f, a1 = 0.f;
    {
        const float4* lrow = (const float4*)&Lsm[tid*LSTR];
        const float4* t0p  = (const float4*)&zqS[0];
        const float4* t1p  = (const float4*)&zqS[DD];
        #pragma unroll
        for (int q = 0; q < 16; q++) {
            float4 l  = lrow[q];
            float4 t0 = t0p[q];
            float4 t1 = t1p[q];
            a0 += l.x*t0.x + l.y*t0.y + l.z*t0.z + l.w*t0.w;
            a1 += l.x*t1.x + l.y*t1.y + l.z*t1.z + l.w*t1.w;
        }
    }
    a0 *= 0.125f; a1 *= 0.125f;   // 1/sqrt(64)

    // block max
    {
        float mx0 = a0, mx1 = a1;
        #pragma unroll
        for (int o = 16; o > 0; o >>= 1) {
            mx0 = fmaxf(mx0, __shfl_xor_sync(0xFFFFFFFFu, mx0, o));
            mx1 = fmaxf(mx1, __shfl_xor_sync(0xFFFFFFFFu, mx1, o));
        }
        if (lane == 0) red2[wid] = make_float2(mx0, mx1);
    }
    __syncthreads();
    if (tid < 32) {
        float2 v = (lane < 16) ? red2[lane] : make_float2(-1e30f, -1e30f);
        #pragma unroll
        for (int o = 8; o > 0; o >>= 1) {
            v.x = fmaxf(v.x, __shfl_xor_sync(0xFFFFFFFFu, v.x, o));
            v.y = fmaxf(v.y, __shfl_xor_sync(0xFFFFFFFFu, v.y, o));
        }
        if (lane == 0) red2[16] = v;
    }
    __syncthreads();
    float2 MX = red2[16];

    // exp + block sum
    float e0 = __expf(a0 - MX.x);
    float e1 = __expf(a1 - MX.y);
    pS2[tid] = make_float2(e0, e1);
    {
        float s0 = e0, s1 = e1;
        #pragma unroll
        for (int o = 16; o > 0; o >>= 1) {
            s0 += __shfl_xor_sync(0xFFFFFFFFu, s0, o);
            s1 += __shfl_xor_sync(0xFFFFFFFFu, s1, o);
        }
        if (lane == 0) red2[wid] = make_float2(s0, s1);
    }
    __syncthreads();
    if (tid < 32) {
        float2 v = (lane < 16) ? red2[lane] : make_float2(0.f, 0.f);
        #pragma unroll
        for (int o = 8; o > 0; o >>= 1) {
            v.x += __shfl_xor_sync(0xFFFFFFFFu, v.x, o);
            v.y += __shfl_xor_sync(0xFFFFFFFFu, v.y, o);
        }
        if (lane == 0) red2[17] = v;
    }
    __syncthreads();
    float2 SUM = red2[17];

    // retrieval: part[c][d] = sum over 64 m of p[m]*L[m][d]
    {
        int d = tid & 63, c = tid >> 6;   // 8 chunks of 64 m
        float r0 = 0.f, r1 = 0.f;
        int m0 = c * 64;
        #pragma unroll 8
        for (int mm = 0; mm < 64; mm++) {
            float2 p = pS2[m0 + mm];              // broadcast
            float  l = Lsm[(m0 + mm)*LSTR + d];   // conflict-free
            r0 += p.x*l; r1 += p.y*l;
        }
        part2[c*64 + d] = make_float2(r0, r1);
    }
    __syncthreads();
    if (tid < NTOK*DD) {
        int j = tid >> 6, d = tid & 63;
        const float* pf = (const float*)part2;
        float s = 0.f;
        #pragma unroll
        for (int c = 0; c < 8; c++)
            s += pf[(c*64 + d)*2 + j];
        float inv = 1.f / (j ? SUM.y : SUM.x);
        zqS[j*DD + d] = s * inv;                  // tmp[j][d] (zqS reused)
    }
    __syncthreads();

    // projection 1: s1[j][f] = sum_d tmp[j][d] * Wv[d][f]
    if (tid < NTOK*DD) {
        int j = tid >> 6, f = tid & 63;
        float s = 0.f;
        const float* tp = &zqS[j*DD];
        #pragma unroll 16
        for (int d = 0; d < DD; d++)
            s += tp[d] * WvS[d*DD + f];           // bcast + conflict-free
        s1S[j*DD + f] = s;
    }
    __syncthreads();

    // projection 2: out[j][e] = sum_f s1[j][f] * Wo[f][e]
    if (tid < NTOK*DD) {
        int j = tid >> 6, e = tid & 63;
        float o = 0.f;
        const float* sp = &s1S[j*DD];
        #pragma unroll 16
        for (int f = 0; f < DD; f++)
            o += sp[f] * WoS[f*DD + e];
        ((float*)&oS2[e])[j] = o;
    }
    __syncthreads();
    if (tid < DD) {
        float2 ov = oS2[tid];
        *(float2*)&out[(b*C2 + tid)*64 + n0] = ov;
    }
}

// ---------------------------------------------------------------------------
extern "C" void kernel_launch(void* const* d_in, const int* in_sizes, int n_in,
                              void* d_out, int out_size) {
    const float* x       = (const float*)d_in[0];
    const float* conv1_w = (const float*)d_in[1];
    const float* conv1_b = (const float*)d_in[2];
    const float* conv2_w = (const float*)d_in[3];
    const float* conv2_b = (const float*)d_in[4];
    const float* lookup  = (const float*)d_in[5];
    const float* Wv      = (const float*)d_in[6];
    const float* Wo      = (const float*)d_in[7];
    float* out = (float*)d_out;

    const size_t smem_bytes = SMEM_FLOATS * sizeof(float);

    cudaFuncSetAttribute(fused_kernel,
                         cudaFuncAttributeMaxDynamicSharedMemorySize,
                         (int)smem_bytes);
    cudaFuncSetAttribute(fused_kernel,
                         cudaFuncAttributePreferredSharedMemoryCarveout, 100);

    fused_kernel<<<NBLK, THR, smem_bytes>>>(
        x, conv1_w, conv1_b, conv2_w, conv2_b, lookup, Wv, Wo, out);
}